// round 7
// baseline (speedup 1.0000x reference)
#include <cuda_runtime.h>
#include <cstdint>

typedef unsigned long long u64;
typedef unsigned int u32;

#define N_ENT   50000
#define N_EDGES 800000
#define NQ      (N_EDGES/4)    // 200000 edge quads
#define NH      (NQ/2)         // 100000: gated threads (2 quads each)
#define D_PE    16
#define NW32    1564           // ceil(50000/32), even

// ---- device state (no allocations allowed) --------------------------------
__device__ ulonglong2 g_state[N_ENT];   // .x = frontier bits, .y = visited bits
__device__ u64 g_next[N_ENT];
__device__ u64 g_cnt[N_ENT];            // packed byte counts c0|c1<<8|c2<<16|c3<<24
__device__ u32 g_Fbm[NW32];             // frontier-nonempty bitmap (rounds 1-2)
__device__ int g_nvalid;

__device__ __forceinline__ ulonglong2 ldcg128(const ulonglong2* p) {
    ulonglong2 r;
    asm volatile("ld.global.cg.v2.u64 {%0,%1}, [%2];"
                 : "=l"(r.x), "=l"(r.y) : "l"(p));
    return r;
}

// ---------------------------------------------------------------------------
// Zero state + seed anchors (owner-block writes, ordered by __syncthreads).
__global__ void k_init(const int* __restrict__ h, const int* __restrict__ t,
                       const int* __restrict__ aidx) {
    __shared__ int svals[64];
    __shared__ int scnt;
    const int tid  = threadIdx.x;
    const int blk  = blockIdx.x;
    const int gtid = blk * 256 + tid;

    if (gtid < N_ENT) {
        g_state[gtid] = make_ulonglong2(0ull, 0ull);
        g_next[gtid]  = 0ull;
        g_cnt[gtid]   = 0ull;
    }
    if (tid < 8) {
        int w = blk * 8 + tid;
        if (w < NW32) g_Fbm[w] = 0u;
    }
    if (tid == 0) scnt = 0;
    if (tid < 64) {
        int e = __ldg(aidx + (tid & 31));
        svals[tid] = (tid < 32) ? __ldg(h + e) : __ldg(t + e);
    }
    __syncthreads();
    if (tid < 64) {
        int v = svals[tid];
        bool uniq = true;
        for (int j = 0; j < tid; j++) if (svals[j] == v) uniq = false;
        if (uniq) {
            if ((v >> 8) == blk) {               // owner block: ordered writes
                u64 bit = 1ull << tid;
                g_state[v] = make_ulonglong2(bit, bit);
                g_cnt[v]   = 1ull;
                atomicOr(&g_Fbm[v >> 5], 1u << (v & 31));
            }
            if (blk == 0) atomicAdd(&scnt, 1);
        }
    }
    __syncthreads();
    if (blk == 0 && tid == 0) g_nvalid = scnt;
}

// ---------------------------------------------------------------------------
// Sparse rounds (1-2): smem bitmap (random LDS ~4cyc vs ~27 L1 wavefronts),
// 8 edges/thread over two coalesced quad streams, rare slow path.
__global__ void __launch_bounds__(512)
k_prop_gated(const int* __restrict__ h, const int* __restrict__ t) {
    __shared__ u32 sF[NW32];
    const int tid = threadIdx.x;
    #pragma unroll
    for (int i = tid; i < NW32; i += 512) sF[i] = __ldcg(&g_Fbm[i]);
    __syncthreads();

    const int g = blockIdx.x * 512 + tid;
    if (g >= NH) return;

    #pragma unroll
    for (int half = 0; half < 2; half++) {
        int j = g + half * NH;                  // two coalesced streams
        int4 S = __ldg((const int4*)h + j);
        int4 D = __ldg((const int4*)t + j);
        #pragma unroll
        for (int q = 0; q < 4; q++) {
            int s = (q == 0) ? S.x : (q == 1) ? S.y : (q == 2) ? S.z : S.w;
            int d = (q == 0) ? D.x : (q == 1) ? D.y : (q == 2) ? D.z : D.w;
            u32 fS = (sF[s >> 5] >> (s & 31)) & 1u;
            u32 fD = (sF[d >> 5] >> (d & 31)) & 1u;
            if (fS | fD) {
                ulonglong2 a = ldcg128(&g_state[s]);
                ulonglong2 b = ldcg128(&g_state[d]);
                if (fS) { u64 nb = a.x & ~b.y; if (nb) atomicOr(&g_next[d], nb); }
                if (fD) { u64 nb = b.x & ~a.y; if (nb) atomicOr(&g_next[s], nb); }
            }
        }
    }
}

// ---------------------------------------------------------------------------
// Dense rounds (3-4): 4 edges/thread, 8 unconditional MLP-batched 16B gathers,
// dedup'd conditional RED.ORs.
__global__ void __launch_bounds__(256)
k_prop_dense(const int* __restrict__ h, const int* __restrict__ t) {
    int j = blockIdx.x * 256 + threadIdx.x;
    if (j >= NQ) return;
    int4 S = __ldg((const int4*)h + j);
    int4 D = __ldg((const int4*)t + j);

    ulonglong2 a0 = ldcg128(&g_state[S.x]);
    ulonglong2 b0 = ldcg128(&g_state[D.x]);
    ulonglong2 a1 = ldcg128(&g_state[S.y]);
    ulonglong2 b1 = ldcg128(&g_state[D.y]);
    ulonglong2 a2 = ldcg128(&g_state[S.z]);
    ulonglong2 b2 = ldcg128(&g_state[D.z]);
    ulonglong2 a3 = ldcg128(&g_state[S.w]);
    ulonglong2 b3 = ldcg128(&g_state[D.w]);

    u64 nb;
    nb = a0.x & ~b0.y; if (nb) atomicOr(&g_next[D.x], nb);
    nb = b0.x & ~a0.y; if (nb) atomicOr(&g_next[S.x], nb);
    nb = a1.x & ~b1.y; if (nb) atomicOr(&g_next[D.y], nb);
    nb = b1.x & ~a1.y; if (nb) atomicOr(&g_next[S.y], nb);
    nb = a2.x & ~b2.y; if (nb) atomicOr(&g_next[D.z], nb);
    nb = b2.x & ~a2.y; if (nb) atomicOr(&g_next[S.z], nb);
    nb = a3.x & ~b3.y; if (nb) atomicOr(&g_next[D.w], nb);
    nb = b3.x & ~a3.y; if (nb) atomicOr(&g_next[S.w], nb);
}

// ---------------------------------------------------------------------------
// Fold next -> {front, vis}; rebuild bitmap only when next round is gated.
__global__ void __launch_bounds__(256)
k_update(int shift, int build_bm) {
    const int gw   = blockIdx.x * 8 + (threadIdx.x >> 5);
    const int lane = threadIdx.x & 31;
    const int n    = gw * 32 + lane;
    u64 nw = 0;
    if (n < N_ENT) {
        u64 nf = __ldcg(&g_next[n]);
        if (nf) {
            g_next[n] = 0ull;
            u64 v = __ldcg(&g_state[n].y);
            nw = nf & ~v;
            if (nw) {
                g_state[n] = make_ulonglong2(nw, v | nw);
                g_cnt[n]  += (u64)__popcll(nw) << shift;
            }
        }
    }
    if (build_bm) {
        u32 bal = __ballot_sync(0xffffffffu, nw != 0);
        if (lane == 0 && gw < NW32) g_Fbm[gw] = bal;
    }
}

// ---------------------------------------------------------------------------
// Depth-4 count + embedding combine.
__global__ void __launch_bounds__(256)
k_final(const float* __restrict__ embed, float* __restrict__ out) {
    __shared__ float sE[6 * D_PE];
    const int tid = threadIdx.x;
    if (tid < 6 * D_PE) sE[tid] = __ldg(embed + tid);
    __syncthreads();
    int n = blockIdx.x * 256 + tid;
    if (n >= N_ENT) return;

    u64 nf = __ldcg(&g_next[n]);
    u64 v  = __ldcg(&g_state[n].y);
    u64 c  = __ldcg(&g_cnt[n]);
    int c4 = __popcll(nf & ~v);
    int c0 = (int)( c        & 0xFF);
    int c1 = (int)((c >> 8)  & 0xFF);
    int c2 = (int)((c >> 16) & 0xFF);
    int c3 = (int)((c >> 24) & 0xFF);
    int nv = g_nvalid;
    int rem = nv - (c0 + c1 + c2 + c3 + c4);
    float inv = 1.0f / (float)nv;
    float w0 = c0 * inv, w1 = c1 * inv, w2 = c2 * inv;
    float w3 = c3 * inv, w4 = c4 * inv, w5 = rem * inv;

    float4* o = (float4*)(out + (size_t)n * D_PE);
#pragma unroll
    for (int q = 0; q < 4; q++) {
        float4 r;
        int b = q * 4;
        r.x = w0*sE[b+0] + w1*sE[D_PE+b+0] + w2*sE[2*D_PE+b+0]
            + w3*sE[3*D_PE+b+0] + w4*sE[4*D_PE+b+0] + w5*sE[5*D_PE+b+0];
        r.y = w0*sE[b+1] + w1*sE[D_PE+b+1] + w2*sE[2*D_PE+b+1]
            + w3*sE[3*D_PE+b+1] + w4*sE[4*D_PE+b+1] + w5*sE[5*D_PE+b+1];
        r.z = w0*sE[b+2] + w1*sE[D_PE+b+2] + w2*sE[2*D_PE+b+2]
            + w3*sE[3*D_PE+b+2] + w4*sE[4*D_PE+b+2] + w5*sE[5*D_PE+b+2];
        r.w = w0*sE[b+3] + w1*sE[D_PE+b+3] + w2*sE[2*D_PE+b+3]
            + w3*sE[3*D_PE+b+3] + w4*sE[4*D_PE+b+3] + w5*sE[5*D_PE+b+3];
        o[q] = r;
    }
}

// ---------------------------------------------------------------------------
extern "C" void kernel_launch(void* const* d_in, const int* in_sizes, int n_in,
                              void* d_out, int out_size) {
    const int*   h     = (const int*)d_in[0];   // [800000]
    const int*   t     = (const int*)d_in[1];   // [800000]
    const int*   aidx  = (const int*)d_in[2];   // [32]
    const float* embed = (const float*)d_in[4]; // [6,16]
    float*       out   = (float*)d_out;         // [50000,16]

    const int GN = (N_ENT + 255) / 256;   // 196
    const int GU = (N_ENT + 255) / 256;   // 196 (8 warps * 32 lanes)
    const int GG = (NH + 511) / 512;      // 196 (gated: 8 edges/thread)
    const int GQ = (NQ + 255) / 256;      // 782 (dense: 4 edges/thread)

    k_init<<<GN, 256>>>(h, t, aidx);

    k_prop_gated<<<GG, 512>>>(h, t);      // depth 1 (sparse)
    k_update<<<GU, 256>>>(8 * 1, 1);      // build bitmap for depth 2

    k_prop_gated<<<GG, 512>>>(h, t);      // depth 2 (sparse)
    k_update<<<GU, 256>>>(8 * 2, 0);

    k_prop_dense<<<GQ, 256>>>(h, t);      // depth 3 (dense)
    k_update<<<GU, 256>>>(8 * 3, 0);

    k_prop_dense<<<GQ, 256>>>(h, t);      // depth 4 (dense)
    k_final<<<GN, 256>>>(embed, out);     // fused depth-4 count + output
}

// round 8
// speedup vs baseline: 1.1734x; 1.1734x over previous
#include <cuda_runtime.h>
#include <cstdint>

typedef unsigned long long u64;
typedef unsigned int u32;

#define N_ENT   50000
#define N_EDGES 800000
#define NQ      (N_EDGES/4)    // 200000 edge quads
#define D_PE    16
#define NW32    1564           // ceil(50000/32), == 391*4

// ---- device state (no allocations allowed) --------------------------------
__device__ ulonglong2 g_state[N_ENT];   // .x = frontier bits, .y = visited bits
__device__ u64 g_next[N_ENT];
__device__ u64 g_cnt[N_ENT];            // packed byte counts c0|c1<<8|c2<<16|c3<<24
__device__ u32 g_Fbm[NW32];             // frontier-nonempty bitmap (rounds 1-2)
__device__ int g_nvalid;

__device__ __forceinline__ ulonglong2 ldcg128(const ulonglong2* p) {
    ulonglong2 r;
    asm volatile("ld.global.cg.v2.u64 {%0,%1}, [%2];"
                 : "=l"(r.x), "=l"(r.y) : "l"(p));
    return r;
}
__device__ __forceinline__ void pdl_wait() {
    asm volatile("griddepcontrol.wait;" ::: "memory");
}

// ---------------------------------------------------------------------------
// Zero state + seed anchors (owner-block writes, ordered by __syncthreads).
__global__ void k_init(const int* __restrict__ h, const int* __restrict__ t,
                       const int* __restrict__ aidx) {
    __shared__ int svals[64];
    __shared__ int scnt;
    const int tid  = threadIdx.x;
    const int blk  = blockIdx.x;
    const int gtid = blk * 256 + tid;

    if (gtid < N_ENT) {
        g_state[gtid] = make_ulonglong2(0ull, 0ull);
        g_next[gtid]  = 0ull;
        g_cnt[gtid]   = 0ull;
    }
    if (tid < 8) {
        int w = blk * 8 + tid;
        if (w < NW32) g_Fbm[w] = 0u;
    }
    if (tid == 0) scnt = 0;
    if (tid < 64) {
        int e = __ldg(aidx + (tid & 31));
        svals[tid] = (tid < 32) ? __ldg(h + e) : __ldg(t + e);
    }
    __syncthreads();
    if (tid < 64) {
        int v = svals[tid];
        bool uniq = true;
        for (int j = 0; j < tid; j++) if (svals[j] == v) uniq = false;
        if (uniq) {
            if ((v >> 8) == blk) {               // owner block: ordered writes
                u64 bit = 1ull << tid;
                g_state[v] = make_ulonglong2(bit, bit);
                g_cnt[v]   = 1ull;
                atomicOr(&g_Fbm[v >> 5], 1u << (v & 31));
            }
            if (blk == 0) atomicAdd(&scnt, 1);
        }
    }
    __syncthreads();
    if (blk == 0 && tid == 0) g_nvalid = scnt;
}

// ---------------------------------------------------------------------------
// Sparse rounds (1-2): 391 blocks x 512 thr, smem bitmap (one uint4 preload
// per thread), 4 edges/thread. Edge quads loaded BEFORE griddepcontrol.wait.
__global__ void __launch_bounds__(512)
k_prop_gated(const int* __restrict__ h, const int* __restrict__ t) {
    __shared__ u32 sF[NW32];
    const int tid = threadIdx.x;
    const int j   = blockIdx.x * 512 + tid;
    const bool act = (j < NQ);
    int4 S, D;
    if (act) {                       // input-only: safe pre-dependency
        S = __ldg((const int4*)h + j);
        D = __ldg((const int4*)t + j);
    }
    pdl_wait();                      // predecessor state now visible
    if (tid < NW32 / 4)
        ((uint4*)sF)[tid] = __ldcg((const uint4*)g_Fbm + tid);
    __syncthreads();
    if (!act) return;

    #pragma unroll
    for (int q = 0; q < 4; q++) {
        int s = (q == 0) ? S.x : (q == 1) ? S.y : (q == 2) ? S.z : S.w;
        int d = (q == 0) ? D.x : (q == 1) ? D.y : (q == 2) ? D.z : D.w;
        u32 fS = (sF[s >> 5] >> (s & 31)) & 1u;
        u32 fD = (sF[d >> 5] >> (d & 31)) & 1u;
        if (fS | fD) {
            ulonglong2 a = ldcg128(&g_state[s]);
            ulonglong2 b = ldcg128(&g_state[d]);
            if (fS) { u64 nb = a.x & ~b.y; if (nb) atomicOr(&g_next[d], nb); }
            if (fD) { u64 nb = b.x & ~a.y; if (nb) atomicOr(&g_next[s], nb); }
        }
    }
}

// ---------------------------------------------------------------------------
// Dense rounds (3-4): 4 edges/thread, 8 MLP-batched 16B gathers, dedup'd
// conditional RED.ORs. Edge quads loaded before the dependency wait.
__global__ void __launch_bounds__(256)
k_prop_dense(const int* __restrict__ h, const int* __restrict__ t) {
    int j = blockIdx.x * 256 + threadIdx.x;
    if (j >= NQ) { pdl_wait(); return; }
    int4 S = __ldg((const int4*)h + j);
    int4 D = __ldg((const int4*)t + j);
    pdl_wait();

    ulonglong2 a0 = ldcg128(&g_state[S.x]);
    ulonglong2 b0 = ldcg128(&g_state[D.x]);
    ulonglong2 a1 = ldcg128(&g_state[S.y]);
    ulonglong2 b1 = ldcg128(&g_state[D.y]);
    ulonglong2 a2 = ldcg128(&g_state[S.z]);
    ulonglong2 b2 = ldcg128(&g_state[D.z]);
    ulonglong2 a3 = ldcg128(&g_state[S.w]);
    ulonglong2 b3 = ldcg128(&g_state[D.w]);

    u64 nb;
    nb = a0.x & ~b0.y; if (nb) atomicOr(&g_next[D.x], nb);
    nb = b0.x & ~a0.y; if (nb) atomicOr(&g_next[S.x], nb);
    nb = a1.x & ~b1.y; if (nb) atomicOr(&g_next[D.y], nb);
    nb = b1.x & ~a1.y; if (nb) atomicOr(&g_next[S.y], nb);
    nb = a2.x & ~b2.y; if (nb) atomicOr(&g_next[D.z], nb);
    nb = b2.x & ~a2.y; if (nb) atomicOr(&g_next[S.z], nb);
    nb = a3.x & ~b3.y; if (nb) atomicOr(&g_next[D.w], nb);
    nb = b3.x & ~a3.y; if (nb) atomicOr(&g_next[S.w], nb);
}

// ---------------------------------------------------------------------------
// Fold next -> {front, vis}; rebuild bitmap only when next round is gated.
__global__ void __launch_bounds__(256)
k_update(int shift, int build_bm) {
    pdl_wait();
    const int gw   = blockIdx.x * 8 + (threadIdx.x >> 5);
    const int lane = threadIdx.x & 31;
    const int n    = gw * 32 + lane;
    u64 nw = 0;
    if (n < N_ENT) {
        u64 nf = __ldcg(&g_next[n]);
        if (nf) {
            g_next[n] = 0ull;
            u64 v = __ldcg(&g_state[n].y);
            nw = nf & ~v;
            if (nw) {
                g_state[n] = make_ulonglong2(nw, v | nw);
                g_cnt[n]  += (u64)__popcll(nw) << shift;
            }
        }
    }
    if (build_bm) {
        u32 bal = __ballot_sync(0xffffffffu, nw != 0);
        if (lane == 0 && gw < NW32) g_Fbm[gw] = bal;
    }
}

// ---------------------------------------------------------------------------
// Depth-4 count + embedding combine.
__global__ void __launch_bounds__(256)
k_final(const float* __restrict__ embed, float* __restrict__ out) {
    __shared__ float sE[6 * D_PE];
    const int tid = threadIdx.x;
    if (tid < 6 * D_PE) sE[tid] = __ldg(embed + tid);   // input-only
    pdl_wait();
    __syncthreads();
    int n = blockIdx.x * 256 + tid;
    if (n >= N_ENT) return;

    u64 nf = __ldcg(&g_next[n]);
    u64 v  = __ldcg(&g_state[n].y);
    u64 c  = __ldcg(&g_cnt[n]);
    int c4 = __popcll(nf & ~v);
    int c0 = (int)( c        & 0xFF);
    int c1 = (int)((c >> 8)  & 0xFF);
    int c2 = (int)((c >> 16) & 0xFF);
    int c3 = (int)((c >> 24) & 0xFF);
    int nv = g_nvalid;
    int rem = nv - (c0 + c1 + c2 + c3 + c4);
    float inv = 1.0f / (float)nv;
    float w0 = c0 * inv, w1 = c1 * inv, w2 = c2 * inv;
    float w3 = c3 * inv, w4 = c4 * inv, w5 = rem * inv;

    float4* o = (float4*)(out + (size_t)n * D_PE);
#pragma unroll
    for (int q = 0; q < 4; q++) {
        float4 r;
        int b = q * 4;
        r.x = w0*sE[b+0] + w1*sE[D_PE+b+0] + w2*sE[2*D_PE+b+0]
            + w3*sE[3*D_PE+b+0] + w4*sE[4*D_PE+b+0] + w5*sE[5*D_PE+b+0];
        r.y = w0*sE[b+1] + w1*sE[D_PE+b+1] + w2*sE[2*D_PE+b+1]
            + w3*sE[3*D_PE+b+1] + w4*sE[4*D_PE+b+1] + w5*sE[5*D_PE+b+1];
        r.z = w0*sE[b+2] + w1*sE[D_PE+b+2] + w2*sE[2*D_PE+b+2]
            + w3*sE[3*D_PE+b+2] + w4*sE[4*D_PE+b+2] + w5*sE[5*D_PE+b+2];
        r.w = w0*sE[b+3] + w1*sE[D_PE+b+3] + w2*sE[2*D_PE+b+3]
            + w3*sE[3*D_PE+b+3] + w4*sE[4*D_PE+b+3] + w5*sE[5*D_PE+b+3];
        o[q] = r;
    }
}

// ---------------------------------------------------------------------------
// PDL launch helper: dependent kernel may start (and run its input prologue)
// while the predecessor finishes; griddepcontrol.wait orders the rest.
template <typename... Args>
static inline void launch_pdl(void (*kern)(Args...), dim3 grid, dim3 block,
                              Args... args) {
    cudaLaunchAttribute attr;
    attr.id = cudaLaunchAttributeProgrammaticStreamSerialization;
    attr.val.programmaticStreamSerializationAllowed = 1;
    cudaLaunchConfig_t cfg = {};
    cfg.gridDim  = grid;
    cfg.blockDim = block;
    cfg.dynamicSmemBytes = 0;
    cfg.stream   = 0;
    cfg.attrs    = &attr;
    cfg.numAttrs = 1;
    cudaLaunchKernelEx(&cfg, kern, args...);
}

extern "C" void kernel_launch(void* const* d_in, const int* in_sizes, int n_in,
                              void* d_out, int out_size) {
    const int*   h     = (const int*)d_in[0];   // [800000]
    const int*   t     = (const int*)d_in[1];   // [800000]
    const int*   aidx  = (const int*)d_in[2];   // [32]
    const float* embed = (const float*)d_in[4]; // [6,16]
    float*       out   = (float*)d_out;         // [50000,16]

    const dim3 B256(256), B512(512);
    const dim3 GN(196);                         // entity-parallel, 256 thr
    const dim3 GG((NQ + 511) / 512);            // 391 gated blocks, 512 thr
    const dim3 GQ((NQ + 255) / 256);            // 782 dense blocks, 256 thr

    k_init<<<GN, B256>>>(h, t, aidx);

    launch_pdl(k_prop_gated, GG, B512, h, t);           // depth 1 (sparse)
    launch_pdl(k_update,     GN, B256, 8 * 1, 1);       // + bitmap for depth 2

    launch_pdl(k_prop_gated, GG, B512, h, t);           // depth 2 (sparse)
    launch_pdl(k_update,     GN, B256, 8 * 2, 0);

    launch_pdl(k_prop_dense, GQ, B256, h, t);           // depth 3 (dense)
    launch_pdl(k_update,     GN, B256, 8 * 3, 0);

    launch_pdl(k_prop_dense, GQ, B256, h, t);           // depth 4 (dense)
    launch_pdl(k_final,      GN, B256, embed, out);     // fused count + output
}